// round 16
// baseline (speedup 1.0000x reference)
#include <cuda_runtime.h>
#include <math.h>

#define BB 16
#define PP 500
#define NN 501
#define EE 128
#define HH 8
#define HD 16
#define LL 3
#define LEAKY 0.2f
#define LN_EPS 1e-5f
#define IT 32
#define JT 16
#define MW 16    // mask words per row (501 bits -> 16 u32)
#define PH 32    // p head stride (floats)
#define PJ 260   // p jj stride (floats) = 8*32+4  (mod 32 == 4 -> conflict-free)
#define NROWS (BB * NN)          // 8016
#define NFACT (BB * NN * HH)     // 64128
#define XWROWS 32
#define XWGRID ((NROWS + XWROWS - 1) / XWROWS)   // 251
#define XW_SMEM ((EE * EE + XWROWS * EE) * 4)    // 80 KB
// attn dynamic smem layout (floats)
#define AOFF_XS 0
#define AOFF_P  (JT * EE)
#define ATTN_SMEM ((JT * EE + JT * PJ) * 4)      // 24832 B

// Scratch (device globals; no runtime allocation)
__device__ float g_x[2][(size_t)BB * NN * EE];
__device__ float g_xW[(size_t)BB * NN * EE];
__device__ float g_ei[NFACT];
__device__ float g_ej[NFACT];
__device__ float g_gmax[BB * HH];
__device__ float g_Q[NFACT], g_S[NFACT];
__device__ float g_Pi[NFACT], g_Ri[NFACT], g_Ti[NFACT];
__device__ unsigned int g_adjbits[BB * NN * MW];
__device__ int g_mask_kind;

// FFMA-only exp, rel err ~2e-7, no MUFU.
__device__ __forceinline__ float fast_exp(float x) {
    x = fmaxf(x, -80.f);
    float y = x * 1.4426950408889634f;
    float t = y + 12582912.f;
    int n = __float_as_int(t) - 0x4B400000;
    float f = y - (t - 12582912.f);
    float u = f * 0.6931471805599453f;
    float r = fmaf(u, 1.38888889e-3f, 8.33333333e-3f);
    r = fmaf(r, u, 4.16666667e-2f);
    r = fmaf(r, u, 1.66666667e-1f);
    r = fmaf(r, u, 0.5f);
    r = fmaf(r, u, 1.0f);
    r = fmaf(r, u, 1.0f);
    return r * __int_as_float((n + 127) << 23);
}
__device__ __forceinline__ float fsel_ge(float a, float b, float thr) {
    return (a >= thr) ? a : b;
}

// ---------------------------------------------------------------------------
__global__ void probe_mask_kernel(const unsigned int* __restrict__ w) {
    __shared__ int s_u8, s_f32;
    if (threadIdx.x == 0) { s_u8 = 0; s_f32 = 0; }
    __syncthreads();
    for (int idx = threadIdx.x; idx < 4096; idx += blockDim.x) {
        unsigned int v = w[idx];
        if (v == 0x3f800000u) atomicOr(&s_f32, 1);
        else if (v > 1u)      atomicOr(&s_u8, 1);
    }
    __syncthreads();
    if (threadIdx.x == 0) g_mask_kind = s_f32 ? 2 : (s_u8 ? 1 : 0);
}

__global__ void convert_bits_kernel(const void* __restrict__ adj_raw) {
    int bn = blockIdx.x;
    int t = threadIdx.x;
    int kind = g_mask_kind;
    bool v = false;
    if (t < NN) {
        size_t idx = (size_t)bn * NN + t;
        if (kind == 1)      v = ((const unsigned char*)adj_raw)[idx] != 0;
        else if (kind == 2) v = ((const float*)adj_raw)[idx] != 0.0f;
        else                v = ((const int*)adj_raw)[idx] != 0;
    }
    unsigned int word = __ballot_sync(0xffffffffu, v);
    if ((t & 31) == 0) g_adjbits[bn * MW + (t >> 5)] = word;
}

// ---------------------------------------------------------------------------
__global__ void embed_kernel(const float* __restrict__ depot_xy,
                             const float* __restrict__ node5,
                             const float* __restrict__ depW,
                             const float* __restrict__ depb,
                             const float* __restrict__ nodeW,
                             const float* __restrict__ nodeb) {
    int bn = blockIdx.x;
    int b = bn / NN, n = bn % NN;
    int e = threadIdx.x;
    float v;
    if (n == 0) {
        float x0 = depot_xy[b * 2 + 0];
        float x1 = depot_xy[b * 2 + 1];
        v = fmaf(x0, depW[0 * EE + e], fmaf(x1, depW[1 * EE + e], depb[e]));
    } else {
        int p = n - 1;
        const float* f = node5 + ((size_t)b * PP + p) * 5;
        v = nodeb[e];
        #pragma unroll
        for (int k = 0; k < 5; k++) v = fmaf(f[k], nodeW[k * EE + e], v);
    }
    g_x[0][(size_t)bn * EE + e] = v;
}

// ---------------------------------------------------------------------------
// xW = x @ W[l] + fused ei/ej. grid = 251, block = 256, 32 rows/block.
// ---------------------------------------------------------------------------
__global__ void __launch_bounds__(256) xw_kernel(int src,
                                                const float* __restrict__ Wl,
                                                const float* __restrict__ attn_l) {
    extern __shared__ float sm[];
    float* ws = sm;
    float* xs = sm + EE * EE;
    int t = threadIdx.x;
    int row0 = blockIdx.x * XWROWS;

    {
        const float4* W4 = (const float4*)Wl;
        float4* ws4 = (float4*)ws;
        #pragma unroll
        for (int k = 0; k < 16; k++) ws4[t + 256 * k] = W4[t + 256 * k];
        const float4* x4 = (const float4*)(&g_x[src][0] + (size_t)row0 * EE);
        float4* xs4 = (float4*)xs;
        int maxf4 = (NROWS - row0) * (EE / 4);
        #pragma unroll
        for (int k = 0; k < 4; k++) {
            int idx = t + 256 * k;
            xs4[idx] = (idx < maxf4) ? x4[idx] : make_float4(0.f, 0.f, 0.f, 0.f);
        }
    }
    __syncthreads();

    int c4 = t & 31;
    int rg = t >> 5;

    float4 acc[4];
    #pragma unroll
    for (int r = 0; r < 4; r++) acc[r] = make_float4(0.f, 0.f, 0.f, 0.f);

    #pragma unroll 8
    for (int k = 0; k < EE; k += 4) {
        float4 w0 = *(const float4*)&ws[(k + 0) * EE + 4 * c4];
        float4 w1 = *(const float4*)&ws[(k + 1) * EE + 4 * c4];
        float4 w2 = *(const float4*)&ws[(k + 2) * EE + 4 * c4];
        float4 w3 = *(const float4*)&ws[(k + 3) * EE + 4 * c4];
        #pragma unroll
        for (int r = 0; r < 4; r++) {
            float4 xv = *(const float4*)&xs[(rg * 4 + r) * EE + k];
            acc[r].x = fmaf(xv.x, w0.x, acc[r].x);
            acc[r].y = fmaf(xv.x, w0.y, acc[r].y);
            acc[r].z = fmaf(xv.x, w0.z, acc[r].z);
            acc[r].w = fmaf(xv.x, w0.w, acc[r].w);
            acc[r].x = fmaf(xv.y, w1.x, acc[r].x);
            acc[r].y = fmaf(xv.y, w1.y, acc[r].y);
            acc[r].z = fmaf(xv.y, w1.z, acc[r].z);
            acc[r].w = fmaf(xv.y, w1.w, acc[r].w);
            acc[r].x = fmaf(xv.z, w2.x, acc[r].x);
            acc[r].y = fmaf(xv.z, w2.y, acc[r].y);
            acc[r].z = fmaf(xv.z, w2.z, acc[r].z);
            acc[r].w = fmaf(xv.z, w2.w, acc[r].w);
            acc[r].x = fmaf(xv.w, w3.x, acc[r].x);
            acc[r].y = fmaf(xv.w, w3.y, acc[r].y);
            acc[r].z = fmaf(xv.w, w3.z, acc[r].z);
            acc[r].w = fmaf(xv.w, w3.w, acc[r].w);
        }
    }

    int h = c4 >> 2;
    int dq = (c4 & 3) * 4;
    float4 a1 = *(const float4*)&attn_l[h * 2 * HD + dq];
    float4 a2 = *(const float4*)&attn_l[h * 2 * HD + HD + dq];
    #pragma unroll
    for (int r = 0; r < 4; r++) {
        int row = row0 + rg * 4 + r;
        if (row >= NROWS) break;
        *(float4*)(g_xW + (size_t)row * EE + 4 * c4) = acc[r];
        float vi = acc[r].x * a1.x + acc[r].y * a1.y + acc[r].z * a1.z + acc[r].w * a1.w;
        float vj = acc[r].x * a2.x + acc[r].y * a2.y + acc[r].z * a2.z + acc[r].w * a2.w;
        vi += __shfl_xor_sync(0xffffffffu, vi, 1);
        vj += __shfl_xor_sync(0xffffffffu, vj, 1);
        vi += __shfl_xor_sync(0xffffffffu, vi, 2);
        vj += __shfl_xor_sync(0xffffffffu, vj, 2);
        if ((c4 & 3) == 0) {
            g_ei[row * HH + h] = vi;
            g_ej[row * HH + h] = vj;
        }
    }
}

// ---------------------------------------------------------------------------
// Per-batch, per-head global max of ej. grid = BB, block = 256.
// ---------------------------------------------------------------------------
__global__ void gmax_kernel() {
    int b = blockIdx.x;
    int t = threadIdx.x;
    __shared__ float part[32][HH];
    int g = t >> 3, h = t & 7;
    const float* ejb = g_ej + (size_t)b * NN * HH;
    float mx = -INFINITY;
    for (int j = g; j < NN; j += 32) mx = fmaxf(mx, ejb[j * HH + h]);
    part[g][h] = mx;
    __syncthreads();
    if (t < HH) {
        float m = part[0][t];
        #pragma unroll
        for (int g2 = 1; g2 < 32; g2++) m = fmaxf(m, part[g2][t]);
        g_gmax[b * HH + t] = m;
    }
}

// ---------------------------------------------------------------------------
// Global softmax factor tables: Q,S (from ej) and Pi,Ri,Ti (from ei, gmax).
// grid = 251, block = 256.
// ---------------------------------------------------------------------------
__global__ void fact_kernel() {
    int idx = blockIdx.x * 256 + threadIdx.x;
    if (idx >= NFACT) return;
    int h = idx & 7;
    int b = idx / (NN * HH);
    float ei = g_ei[idx], ej = g_ej[idx];
    float gm = g_gmax[b * HH + h];
    float w = ei + gm;
    float m = fmaxf(w, LEAKY * w);
    g_Pi[idx] = fast_exp(ei - m);
    g_Ri[idx] = fast_exp(0.2f * ei - m);
    g_Ti[idx] = fast_exp(-m);
    g_Q[idx] = fast_exp(ej);
    g_S[idx] = fast_exp(0.2f * ej);
}

// ---------------------------------------------------------------------------
// Attention + residual + LayerNorm + ELU. grid = (16, B), block = 256.
// All softmax factors precomputed globally; 24.8 KB dyn smem -> 4 blocks/SM,
// single wave. Warp w == head w; rg = l&7 (rows rg*4..+3), q = l>>3, cg = w*4+q.
// ---------------------------------------------------------------------------
__global__ void __launch_bounds__(256, 4) attn_kernel(const float* __restrict__ gamma,
                                                      const float* __restrict__ beta,
                                                      int dst, float* __restrict__ dout) {
    int b = blockIdx.y;
    int i0 = blockIdx.x * IT;
    int t = threadIdx.x;

    extern __shared__ float dyn[];
    float* xs  = dyn + AOFF_XS;   // [jj][e]
    float* p_s = dyn + AOFF_P;    // [jj*PJ + h*PH + ii]

    __shared__ unsigned int mask_s[IT][MW];
    __shared__ float lnred[8][8][4][2];
    __shared__ float mu_s[IT], rstd_s[IT];

    const float* xWb = g_xW + (size_t)b * NN * EE;

    // mask bits: 512 words
    {
        #pragma unroll
        for (int k = 0; k < 2; k++) {
            int idx = t + 256 * k;
            int ii = idx >> 4, w2 = idx & 15;
            int i = i0 + ii;
            mask_s[ii][w2] = (i < NN) ? g_adjbits[(b * NN + i) * MW + w2] : 0u;
        }
    }

    int w = t >> 5;
    int l = t & 31;
    int rg = l & 7;
    int q = l >> 3;
    int cg = w * 4 + q;
    bool sowner = (q == 0);
    int ii_t = t >> 3;
    int jj_t = t & 7;

    // per-thread row factors from global tables
    float Pi_r[HH], Ri_r[HH], Ti_r[HH];
    {
        int i = i0 + ii_t;
        if (i < NN) {
            size_t o8 = ((size_t)b * NN + i) * HH;
            *(float4*)&Pi_r[0] = *(const float4*)&g_Pi[o8];
            *(float4*)&Pi_r[4] = *(const float4*)&g_Pi[o8 + 4];
            *(float4*)&Ri_r[0] = *(const float4*)&g_Ri[o8];
            *(float4*)&Ri_r[4] = *(const float4*)&g_Ri[o8 + 4];
            *(float4*)&Ti_r[0] = *(const float4*)&g_Ti[o8];
            *(float4*)&Ti_r[4] = *(const float4*)&g_Ti[o8 + 4];
        } else {
            #pragma unroll
            for (int hh = 0; hh < HH; hh++) { Pi_r[hh] = 0.f; Ri_r[hh] = 0.f; Ti_r[hh] = 1.f; }
        }
    }
    __syncthreads();

    const float* Qb = g_Q + (size_t)b * NN * HH;
    const float* Sb = g_S + (size_t)b * NN * HH;

    float4 acc[4];
    float sacc[4];
    #pragma unroll
    for (int r = 0; r < 4; r++) { acc[r] = make_float4(0.f, 0.f, 0.f, 0.f); sacc[r] = 0.f; }

    for (int j0 = 0; j0 < NN; j0 += JT) {
        // fused phase: stage xs + compute p (from global tables)
        {
            float4* d4 = (float4*)xs;
            #pragma unroll
            for (int k = 0; k < 2; k++) {
                int idx = t + 256 * k;
                int jj = idx >> 5;
                int j = j0 + jj;
                d4[idx] = (j < NN) ? ((const float4*)(xWb + (size_t)j * EE))[idx & 31]
                                   : make_float4(0.f, 0.f, 0.f, 0.f);
            }
        }
        #pragma unroll
        for (int k = 0; k < 2; k++) {
            int jj = jj_t + 8 * k;
            int j = j0 + jj;
            float* pd = &p_s[jj * PJ + ii_t];
            if (j < NN && ((mask_s[ii_t][j >> 5] >> (j & 31)) & 1u)) {
                float4 q0 = *(const float4*)&Qb[j * 8];
                float4 q1 = *(const float4*)&Qb[j * 8 + 4];
                float4 sp0 = *(const float4*)&Sb[j * 8];
                float4 sp1 = *(const float4*)&Sb[j * 8 + 4];
                pd[0 * PH] = fsel_ge(Pi_r[0] * q0.x, Ri_r[0] * sp0.x, Ti_r[0]);
                pd[1 * PH] = fsel_ge(Pi_r[1] * q0.y, Ri_r[1] * sp0.y, Ti_r[1]);
                pd[2 * PH] = fsel_ge(Pi_r[2] * q0.z, Ri_r[2] * sp0.z, Ti_r[2]);
                pd[3 * PH] = fsel_ge(Pi_r[3] * q0.w, Ri_r[3] * sp0.w, Ti_r[3]);
                pd[4 * PH] = fsel_ge(Pi_r[4] * q1.x, Ri_r[4] * sp1.x, Ti_r[4]);
                pd[5 * PH] = fsel_ge(Pi_r[5] * q1.y, Ri_r[5] * sp1.y, Ti_r[5]);
                pd[6 * PH] = fsel_ge(Pi_r[6] * q1.z, Ri_r[6] * sp1.z, Ti_r[6]);
                pd[7 * PH] = fsel_ge(Pi_r[7] * q1.w, Ri_r[7] * sp1.w, Ti_r[7]);
            } else {
                #pragma unroll
                for (int hh = 0; hh < HH; hh++) pd[hh * PH] = 0.f;
            }
        }
        __syncthreads();

        #pragma unroll 4
        for (int jj = 0; jj < JT; jj++) {
            float4 p4 = *(const float4*)&p_s[jj * PJ + w * PH + rg * 4];
            float4 xv = *(const float4*)&xs[jj * EE + 4 * cg];
            acc[0].x = fmaf(p4.x, xv.x, acc[0].x);
            acc[0].y = fmaf(p4.x, xv.y, acc[0].y);
            acc[0].z = fmaf(p4.x, xv.z, acc[0].z);
            acc[0].w = fmaf(p4.x, xv.w, acc[0].w);
            acc[1].x = fmaf(p4.y, xv.x, acc[1].x);
            acc[1].y = fmaf(p4.y, xv.y, acc[1].y);
            acc[1].z = fmaf(p4.y, xv.z, acc[1].z);
            acc[1].w = fmaf(p4.y, xv.w, acc[1].w);
            acc[2].x = fmaf(p4.z, xv.x, acc[2].x);
            acc[2].y = fmaf(p4.z, xv.y, acc[2].y);
            acc[2].z = fmaf(p4.z, xv.z, acc[2].z);
            acc[2].w = fmaf(p4.z, xv.w, acc[2].w);
            acc[3].x = fmaf(p4.w, xv.x, acc[3].x);
            acc[3].y = fmaf(p4.w, xv.y, acc[3].y);
            acc[3].z = fmaf(p4.w, xv.z, acc[3].z);
            acc[3].w = fmaf(p4.w, xv.w, acc[3].w);
            if (sowner) {
                sacc[0] += p4.x; sacc[1] += p4.y;
                sacc[2] += p4.z; sacc[3] += p4.w;
            }
        }
        __syncthreads();
    }

    // epilogue: row sums via shuffle (lane rg holds rows rg*4..rg*4+3)
    float4 val[4];
    #pragma unroll
    for (int r = 0; r < 4; r++) {
        float sv = __shfl_sync(0xffffffffu, sacc[r], rg);
        int ii = rg * 4 + r;
        int i = i0 + ii;
        float4 xwv = (i < NN) ? *(const float4*)(xWb + (size_t)i * EE + 4 * cg)
                              : make_float4(0.f, 0.f, 0.f, 0.f);
        float inv = 1.f / sv;
        val[r].x = acc[r].x * inv + xwv.x;
        val[r].y = acc[r].y * inv + xwv.y;
        val[r].z = acc[r].z * inv + xwv.z;
        val[r].w = acc[r].w * inv + xwv.w;
        float s1 = val[r].x + val[r].y + val[r].z + val[r].w;
        float s2 = val[r].x * val[r].x + val[r].y * val[r].y +
                   val[r].z * val[r].z + val[r].w * val[r].w;
        s1 += __shfl_xor_sync(0xffffffffu, s1, 8);
        s2 += __shfl_xor_sync(0xffffffffu, s2, 8);
        s1 += __shfl_xor_sync(0xffffffffu, s1, 16);
        s2 += __shfl_xor_sync(0xffffffffu, s2, 16);
        if (sowner) { lnred[w][rg][r][0] = s1; lnred[w][rg][r][1] = s2; }
    }
    __syncthreads();
    if (t < IT) {
        int rg2 = t >> 2, r2 = t & 3;
        float a = 0.f, qq = 0.f;
        #pragma unroll
        for (int w2 = 0; w2 < 8; w2++) {
            a += lnred[w2][rg2][r2][0];
            qq += lnred[w2][rg2][r2][1];
        }
        float mu = a * (1.f / EE);
        float var = qq * (1.f / EE) - mu * mu;
        mu_s[t] = mu;
        rstd_s[t] = rsqrtf(var + LN_EPS);
    }
    __syncthreads();

    float* o = (dst < 0) ? dout : &g_x[dst][0];
    float4 gv = *(const float4*)&gamma[4 * cg];
    float4 bv = *(const float4*)&beta[4 * cg];
    #pragma unroll
    for (int r = 0; r < 4; r++) {
        int ii = rg * 4 + r;
        int i = i0 + ii;
        if (i >= NN) continue;
        float mu = mu_s[ii], rstd = rstd_s[ii];
        float y0 = (val[r].x - mu) * rstd * gv.x + bv.x;
        float y1 = (val[r].y - mu) * rstd * gv.y + bv.y;
        float y2 = (val[r].z - mu) * rstd * gv.z + bv.z;
        float y3 = (val[r].w - mu) * rstd * gv.w + bv.w;
        y0 = y0 > 0.f ? y0 : (fast_exp(y0) - 1.f);
        y1 = y1 > 0.f ? y1 : (fast_exp(y1) - 1.f);
        y2 = y2 > 0.f ? y2 : (fast_exp(y2) - 1.f);
        y3 = y3 > 0.f ? y3 : (fast_exp(y3) - 1.f);
        *(float4*)(o + ((size_t)(b * NN + i)) * EE + 4 * cg) =
            make_float4(y0, y1, y2, y3);
    }
}

// ---------------------------------------------------------------------------
extern "C" void kernel_launch(void* const* d_in, const int* in_sizes, int n_in,
                              void* d_out, int out_size) {
    const float* depot_xy = (const float*)d_in[0];
    const float* node5    = (const float*)d_in[1];
    const void*  adj_raw  = (const void*)d_in[2];
    const float* depW  = (const float*)d_in[3];
    const float* depb  = (const float*)d_in[4];
    const float* nodeW = (const float*)d_in[5];
    const float* nodeb = (const float*)d_in[6];
    const float* W     = (const float*)d_in[7];
    const float* attn  = (const float*)d_in[8];
    const float* ln_g  = (const float*)d_in[9];
    const float* ln_b  = (const float*)d_in[10];
    float* out = (float*)d_out;

    cudaFuncSetAttribute(xw_kernel,
                         cudaFuncAttributeMaxDynamicSharedMemorySize, XW_SMEM);

    probe_mask_kernel<<<1, 256>>>((const unsigned int*)adj_raw);
    convert_bits_kernel<<<BB * NN, 512>>>(adj_raw);

    embed_kernel<<<BB * NN, EE>>>(depot_xy, node5, depW, depb, nodeW, nodeb);

    dim3 agrid((NN + IT - 1) / IT, BB);
    int cur = 0;
    for (int l = 0; l < LL; l++) {
        xw_kernel<<<XWGRID, 256, XW_SMEM>>>(cur,
                                            W + (size_t)l * EE * EE,
                                            attn + (size_t)l * HH * 2 * HD);
        gmax_kernel<<<BB, 256>>>();
        fact_kernel<<<(NFACT + 255) / 256, 256>>>();
        int dst = (l == LL - 1) ? -1 : (1 - cur);
        attn_kernel<<<agrid, 256, ATTN_SMEM>>>(ln_g + (size_t)l * EE,
                                               ln_b + (size_t)l * EE,
                                               dst, out);
        cur = 1 - cur;
    }
}

// round 17
// speedup vs baseline: 1.1214x; 1.1214x over previous
#include <cuda_runtime.h>
#include <math.h>

#define BB 16
#define PP 500
#define NN 501
#define EE 128
#define HH 8
#define HD 16
#define LL 3
#define LEAKY 0.2f
#define LN_EPS 1e-5f
#define IT 32
#define JT 16
#define ZJ 256   // j-range per z-split
#define MW 16    // mask words per row
#define PH 32    // p head stride (floats)
#define PJ 260   // p jj stride (floats) = 8*32+4
#define NROWS (BB * NN)          // 8016
#define NFACT (BB * NN * HH)     // 64128
#define XWROWS 32
#define XWGRID ((NROWS + XWROWS - 1) / XWROWS)   // 251
#define XW_SMEM ((EE * EE + XWROWS * EE) * 4)    // 80 KB
// attn dynamic smem layout (floats)
#define AOFF_QS 0
#define AOFF_SS (ZJ * HH)            // 2048
#define AOFF_XS (2 * ZJ * HH)        // 4096
#define AOFF_P  (2 * ZJ * HH + JT * EE)  // 6144
#define ATTN_SMEM ((2 * ZJ * HH + JT * EE + JT * PJ) * 4)   // 41216 B

// Scratch (device globals; no runtime allocation)
__device__ float g_x[2][(size_t)BB * NN * EE];
__device__ float g_xW[(size_t)BB * NN * EE];
__device__ float g_part[2][(size_t)BB * NN * EE];
__device__ float g_psum[2][NFACT];
__device__ float g_ei[NFACT];
__device__ float g_ej[NFACT];
__device__ float g_gmax[BB * HH];
__device__ float g_Q[NFACT], g_S[NFACT];
__device__ float g_Pi[NFACT], g_Ri[NFACT], g_Ti[NFACT];
__device__ unsigned int g_adjbits[BB * NN * MW];
__device__ int g_mask_kind;

// FFMA-only exp, rel err ~2e-7, no MUFU.
__device__ __forceinline__ float fast_exp(float x) {
    x = fmaxf(x, -80.f);
    float y = x * 1.4426950408889634f;
    float t = y + 12582912.f;
    int n = __float_as_int(t) - 0x4B400000;
    float f = y - (t - 12582912.f);
    float u = f * 0.6931471805599453f;
    float r = fmaf(u, 1.38888889e-3f, 8.33333333e-3f);
    r = fmaf(r, u, 4.16666667e-2f);
    r = fmaf(r, u, 1.66666667e-1f);
    r = fmaf(r, u, 0.5f);
    r = fmaf(r, u, 1.0f);
    r = fmaf(r, u, 1.0f);
    return r * __int_as_float((n + 127) << 23);
}
__device__ __forceinline__ float fsel_ge(float a, float b, float thr) {
    return (a >= thr) ? a : b;
}

// ---------------------------------------------------------------------------
__global__ void probe_mask_kernel(const unsigned int* __restrict__ w) {
    __shared__ int s_u8, s_f32;
    if (threadIdx.x == 0) { s_u8 = 0; s_f32 = 0; }
    __syncthreads();
    for (int idx = threadIdx.x; idx < 4096; idx += blockDim.x) {
        unsigned int v = w[idx];
        if (v == 0x3f800000u) atomicOr(&s_f32, 1);
        else if (v > 1u)      atomicOr(&s_u8, 1);
    }
    __syncthreads();
    if (threadIdx.x == 0) g_mask_kind = s_f32 ? 2 : (s_u8 ? 1 : 0);
}

__global__ void convert_bits_kernel(const void* __restrict__ adj_raw) {
    int bn = blockIdx.x;
    int t = threadIdx.x;
    int kind = g_mask_kind;
    bool v = false;
    if (t < NN) {
        size_t idx = (size_t)bn * NN + t;
        if (kind == 1)      v = ((const unsigned char*)adj_raw)[idx] != 0;
        else if (kind == 2) v = ((const float*)adj_raw)[idx] != 0.0f;
        else                v = ((const int*)adj_raw)[idx] != 0;
    }
    unsigned int word = __ballot_sync(0xffffffffu, v);
    if ((t & 31) == 0) g_adjbits[bn * MW + (t >> 5)] = word;
}

// ---------------------------------------------------------------------------
__global__ void embed_kernel(const float* __restrict__ depot_xy,
                             const float* __restrict__ node5,
                             const float* __restrict__ depW,
                             const float* __restrict__ depb,
                             const float* __restrict__ nodeW,
                             const float* __restrict__ nodeb) {
    int bn = blockIdx.x;
    int b = bn / NN, n = bn % NN;
    int e = threadIdx.x;
    float v;
    if (n == 0) {
        float x0 = depot_xy[b * 2 + 0];
        float x1 = depot_xy[b * 2 + 1];
        v = fmaf(x0, depW[0 * EE + e], fmaf(x1, depW[1 * EE + e], depb[e]));
    } else {
        int p = n - 1;
        const float* f = node5 + ((size_t)b * PP + p) * 5;
        v = nodeb[e];
        #pragma unroll
        for (int k = 0; k < 5; k++) v = fmaf(f[k], nodeW[k * EE + e], v);
    }
    g_x[0][(size_t)bn * EE + e] = v;
}

// ---------------------------------------------------------------------------
// xW = x @ W[l] + fused ei/ej. grid = 251, block = 256, 32 rows/block.
// ---------------------------------------------------------------------------
__global__ void __launch_bounds__(256) xw_kernel(int src,
                                                const float* __restrict__ Wl,
                                                const float* __restrict__ attn_l) {
    extern __shared__ float sm[];
    float* ws = sm;
    float* xs = sm + EE * EE;
    int t = threadIdx.x;
    int row0 = blockIdx.x * XWROWS;

    {
        const float4* W4 = (const float4*)Wl;
        float4* ws4 = (float4*)ws;
        #pragma unroll
        for (int k = 0; k < 16; k++) ws4[t + 256 * k] = W4[t + 256 * k];
        const float4* x4 = (const float4*)(&g_x[src][0] + (size_t)row0 * EE);
        float4* xs4 = (float4*)xs;
        int maxf4 = (NROWS - row0) * (EE / 4);
        #pragma unroll
        for (int k = 0; k < 4; k++) {
            int idx = t + 256 * k;
            xs4[idx] = (idx < maxf4) ? x4[idx] : make_float4(0.f, 0.f, 0.f, 0.f);
        }
    }
    __syncthreads();

    int c4 = t & 31;
    int rg = t >> 5;

    float4 acc[4];
    #pragma unroll
    for (int r = 0; r < 4; r++) acc[r] = make_float4(0.f, 0.f, 0.f, 0.f);

    #pragma unroll 8
    for (int k = 0; k < EE; k += 4) {
        float4 w0 = *(const float4*)&ws[(k + 0) * EE + 4 * c4];
        float4 w1 = *(const float4*)&ws[(k + 1) * EE + 4 * c4];
        float4 w2 = *(const float4*)&ws[(k + 2) * EE + 4 * c4];
        float4 w3 = *(const float4*)&ws[(k + 3) * EE + 4 * c4];
        #pragma unroll
        for (int r = 0; r < 4; r++) {
            float4 xv = *(const float4*)&xs[(rg * 4 + r) * EE + k];
            acc[r].x = fmaf(xv.x, w0.x, acc[r].x);
            acc[r].y = fmaf(xv.x, w0.y, acc[r].y);
            acc[r].z = fmaf(xv.x, w0.z, acc[r].z);
            acc[r].w = fmaf(xv.x, w0.w, acc[r].w);
            acc[r].x = fmaf(xv.y, w1.x, acc[r].x);
            acc[r].y = fmaf(xv.y, w1.y, acc[r].y);
            acc[r].z = fmaf(xv.y, w1.z, acc[r].z);
            acc[r].w = fmaf(xv.y, w1.w, acc[r].w);
            acc[r].x = fmaf(xv.z, w2.x, acc[r].x);
            acc[r].y = fmaf(xv.z, w2.y, acc[r].y);
            acc[r].z = fmaf(xv.z, w2.z, acc[r].z);
            acc[r].w = fmaf(xv.z, w2.w, acc[r].w);
            acc[r].x = fmaf(xv.w, w3.x, acc[r].x);
            acc[r].y = fmaf(xv.w, w3.y, acc[r].y);
            acc[r].z = fmaf(xv.w, w3.z, acc[r].z);
            acc[r].w = fmaf(xv.w, w3.w, acc[r].w);
        }
    }

    int h = c4 >> 2;
    int dq = (c4 & 3) * 4;
    float4 a1 = *(const float4*)&attn_l[h * 2 * HD + dq];
    float4 a2 = *(const float4*)&attn_l[h * 2 * HD + HD + dq];
    #pragma unroll
    for (int r = 0; r < 4; r++) {
        int row = row0 + rg * 4 + r;
        if (row >= NROWS) break;
        *(float4*)(g_xW + (size_t)row * EE + 4 * c4) = acc[r];
        float vi = acc[r].x * a1.x + acc[r].y * a1.y + acc[r].z * a1.z + acc[r].w * a1.w;
        float vj = acc[r].x * a2.x + acc[r].y * a2.y + acc[r].z * a2.z + acc[r].w * a2.w;
        vi += __shfl_xor_sync(0xffffffffu, vi, 1);
        vj += __shfl_xor_sync(0xffffffffu, vj, 1);
        vi += __shfl_xor_sync(0xffffffffu, vi, 2);
        vj += __shfl_xor_sync(0xffffffffu, vj, 2);
        if ((c4 & 3) == 0) {
            g_ei[row * HH + h] = vi;
            g_ej[row * HH + h] = vj;
        }
    }
}

// ---------------------------------------------------------------------------
// Per-batch, per-head global max of ej. grid = BB, block = 256.
// ---------------------------------------------------------------------------
__global__ void gmax_kernel() {
    int b = blockIdx.x;
    int t = threadIdx.x;
    __shared__ float part[32][HH];
    int g = t >> 3, h = t & 7;
    const float* ejb = g_ej + (size_t)b * NN * HH;
    float mx = -INFINITY;
    for (int j = g; j < NN; j += 32) mx = fmaxf(mx, ejb[j * HH + h]);
    part[g][h] = mx;
    __syncthreads();
    if (t < HH) {
        float m = part[0][t];
        #pragma unroll
        for (int g2 = 1; g2 < 32; g2++) m = fmaxf(m, part[g2][t]);
        g_gmax[b * HH + t] = m;
    }
}

// ---------------------------------------------------------------------------
// Global softmax factor tables. grid = 251, block = 256.
// ---------------------------------------------------------------------------
__global__ void fact_kernel() {
    int idx = blockIdx.x * 256 + threadIdx.x;
    if (idx >= NFACT) return;
    int h = idx & 7;
    int b = idx / (NN * HH);
    float ei = g_ei[idx], ej = g_ej[idx];
    float gm = g_gmax[b * HH + h];
    float w = ei + gm;
    float m = fmaxf(w, LEAKY * w);
    g_Pi[idx] = fast_exp(ei - m);
    g_Ri[idx] = fast_exp(0.2f * ei - m);
    g_Ti[idx] = fast_exp(-m);
    g_Q[idx] = fast_exp(ej);
    g_S[idx] = fast_exp(0.2f * ej);
}

// ---------------------------------------------------------------------------
// Split-j attention partials. grid = (16, B, 2), block = 256.
// z-block covers j in [z*ZJ, min(NN, z*ZJ+ZJ)). Writes unnormalized acc to
// g_part[z] and row sums to g_psum[z] (same global shift m -> partials add).
// Q/S j-slices copied to smem from global tables. 41 KB dyn -> 5 blocks/SM.
// ---------------------------------------------------------------------------
__global__ void __launch_bounds__(256) attn_kernel(int dummy) {
    int b = blockIdx.y;
    int i0 = blockIdx.x * IT;
    int z = blockIdx.z;
    int jbase = z * ZJ;
    int t = threadIdx.x;

    extern __shared__ float dyn[];
    float* Qs  = dyn + AOFF_QS;   // [jl*8 + h], jl local
    float* Ss  = dyn + AOFF_SS;
    float* xs  = dyn + AOFF_XS;   // [jj][e]
    float* p_s = dyn + AOFF_P;    // [jj*PJ + h*PH + ii]

    __shared__ unsigned int mask_s[IT][MW];

    const float* xWb = g_xW + (size_t)b * NN * EE;

    // mask bits
    {
        #pragma unroll
        for (int k = 0; k < 2; k++) {
            int idx = t + 256 * k;
            int ii = idx >> 4, w2 = idx & 15;
            int i = i0 + ii;
            mask_s[ii][w2] = (i < NN) ? g_adjbits[(b * NN + i) * MW + w2] : 0u;
        }
    }
    // copy Q/S j-slice (2048 floats each = 512 float4)
    {
        const float4* Qg = (const float4*)(g_Q + ((size_t)b * NN + jbase) * HH);
        const float4* Sg = (const float4*)(g_S + ((size_t)b * NN + jbase) * HH);
        float4* Qd = (float4*)Qs;
        float4* Sd = (float4*)Ss;
        int nvalid = (NN - jbase < ZJ ? NN - jbase : ZJ) * 2;  // float4 count
        #pragma unroll
        for (int k = 0; k < 2; k++) {
            int idx = t + 256 * k;
            float4 qv = (idx < nvalid) ? Qg[idx] : make_float4(0.f, 0.f, 0.f, 0.f);
            float4 sv = (idx < nvalid) ? Sg[idx] : make_float4(0.f, 0.f, 0.f, 0.f);
            Qd[idx] = qv;
            Sd[idx] = sv;
        }
    }

    int w = t >> 5;
    int l = t & 31;
    int rg = l & 7;
    int q = l >> 3;
    int cg = w * 4 + q;
    bool sowner = (q == 0);
    int ii_t = t >> 3;
    int jj_t = t & 7;

    // per-thread row factors
    float Pi_r[HH], Ri_r[HH], Ti_r[HH];
    {
        int i = i0 + ii_t;
        if (i < NN) {
            size_t o8 = ((size_t)b * NN + i) * HH;
            *(float4*)&Pi_r[0] = *(const float4*)&g_Pi[o8];
            *(float4*)&Pi_r[4] = *(const float4*)&g_Pi[o8 + 4];
            *(float4*)&Ri_r[0] = *(const float4*)&g_Ri[o8];
            *(float4*)&Ri_r[4] = *(const float4*)&g_Ri[o8 + 4];
            *(float4*)&Ti_r[0] = *(const float4*)&g_Ti[o8];
            *(float4*)&Ti_r[4] = *(const float4*)&g_Ti[o8 + 4];
        } else {
            #pragma unroll
            for (int hh = 0; hh < HH; hh++) { Pi_r[hh] = 0.f; Ri_r[hh] = 0.f; Ti_r[hh] = 1.f; }
        }
    }
    __syncthreads();

    float4 acc[4];
    float sacc[4];
    #pragma unroll
    for (int r = 0; r < 4; r++) { acc[r] = make_float4(0.f, 0.f, 0.f, 0.f); sacc[r] = 0.f; }

    #pragma unroll 1
    for (int tile = 0; tile < ZJ / JT; tile++) {
        int j0 = jbase + tile * JT;
        // fused phase: stage xs + compute p (tables in smem)
        {
            float4* d4 = (float4*)xs;
            #pragma unroll
            for (int k = 0; k < 2; k++) {
                int idx = t + 256 * k;
                int jj = idx >> 5;
                int j = j0 + jj;
                d4[idx] = (j < NN) ? ((const float4*)(xWb + (size_t)j * EE))[idx & 31]
                                   : make_float4(0.f, 0.f, 0.f, 0.f);
            }
        }
        #pragma unroll
        for (int k = 0; k < 2; k++) {
            int jj = jj_t + 8 * k;
            int j = j0 + jj;
            int jl = j - jbase;
            float* pd = &p_s[jj * PJ + ii_t];
            if (j < NN && ((mask_s[ii_t][j >> 5] >> (j & 31)) & 1u)) {
                float4 q0 = *(const float4*)&Qs[jl * 8];
                float4 q1 = *(const float4*)&Qs[jl * 8 + 4];
                float4 sp0 = *(const float4*)&Ss[jl * 8];
                float4 sp1 = *(const float4*)&Ss[jl * 8 + 4];
                pd[0 * PH] = fsel_ge(Pi_r[0] * q0.x, Ri_r[0] * sp0.x, Ti_r[0]);
                pd[1 * PH] = fsel_ge(Pi_r[1] * q0.y, Ri_r[1] * sp0.y, Ti_r[1]);
                pd[2 * PH] = fsel_ge(Pi_r[2] * q0.z, Ri_r[2] * sp0.z, Ti_r[2]);
                pd[3 * PH] = fsel_ge(Pi_r[3] * q0.w, Ri_r[3] * sp0.w, Ti_r[3]);
                pd[4 * PH] = fsel_ge(Pi_r[4] * q1.x, Ri_r[4] * sp1.x, Ti_r[4]);
                pd[5 * PH] = fsel_ge(Pi_r[5] * q1.y, Ri_r[5] * sp1.y, Ti_r[5]);
                pd[6 * PH] = fsel_ge(Pi_r[6] * q1.z, Ri_r[6] * sp1.z, Ti_r[6]);
                pd[7 * PH] = fsel_ge(Pi_r[7] * q1.w, Ri_r[7] * sp1.w, Ti_r[7]);
            } else {
                #pragma unroll
                for (int hh = 0; hh < HH; hh++) pd[hh * PH] = 0.f;
            }
        }
        __syncthreads();

        #pragma unroll 4
        for (int jj = 0; jj < JT; jj++) {
            float4 p4 = *(const float4*)&p_s[jj * PJ + w * PH + rg * 4];
            float4 xv = *(const float4*)&xs[jj * EE + 4 * cg];
            acc[0].x = fmaf(p4.x, xv.x, acc[0].x);
            acc[0].y = fmaf(p4.x, xv.y, acc[0].y);
            acc[0].z = fmaf(p4.x, xv.z, acc[0].z);
            acc[0].w = fmaf(p4.x, xv.w, acc[0].w);
            acc[1].x = fmaf(p4.y, xv.x, acc[1].x);
            acc[1].y = fmaf(p4.y, xv.y, acc[1].y);
            acc[1].z = fmaf(p4.y, xv.z, acc[1].z);
            acc[1].w = fmaf(p4.y, xv.w, acc[1].w);
            acc[2].x = fmaf(p4.z, xv.x, acc[2].x);
            acc[2].y = fmaf(p4.z, xv.y, acc[2].y);
            acc[2].z = fmaf(p4.z, xv.z, acc[2].z);
            acc[2].w = fmaf(p4.z, xv.w, acc[2].w);
            acc[3].x = fmaf(p4.w, xv.x, acc[3].x);
            acc[3].y = fmaf(p4.w, xv.y, acc[3].y);
            acc[3].z = fmaf(p4.w, xv.z, acc[3].z);
            acc[3].w = fmaf(p4.w, xv.w, acc[3].w);
            if (sowner) {
                sacc[0] += p4.x; sacc[1] += p4.y;
                sacc[2] += p4.z; sacc[3] += p4.w;
            }
        }
        __syncthreads();
    }

    // write partials
    float* pw = &g_part[z][0];
    #pragma unroll
    for (int r = 0; r < 4; r++) {
        int ii = rg * 4 + r;
        int i = i0 + ii;
        if (i >= NN) continue;
        *(float4*)(pw + ((size_t)b * NN + i) * EE + 4 * cg) = acc[r];
        if (sowner)
            g_psum[z][((size_t)b * NN + i) * HH + w] = sacc[r];
    }
}

// ---------------------------------------------------------------------------
// Combine partials + residual + LayerNorm + ELU. grid = (16, B), block = 256.
// Thread: ii = t>>3 (row), colq = t&7 (cols colq*16..+15 == head colq).
// ---------------------------------------------------------------------------
__global__ void __launch_bounds__(256) combine_kernel(const float* __restrict__ gamma,
                                                      const float* __restrict__ beta,
                                                      int dst, float* __restrict__ dout) {
    int b = blockIdx.y;
    int i0 = blockIdx.x * IT;
    int t = threadIdx.x;
    int ii = t >> 3;
    int colq = t & 7;
    int i = i0 + ii;
    bool valid = (i < NN);
    size_t rowo = ((size_t)b * NN + (valid ? i : 0)) * EE + colq * 16;

    float s = 0.f;
    float4 v[4];
    if (valid) {
        s = g_psum[0][((size_t)b * NN + i) * HH + colq] +
            g_psum[1][((size_t)b * NN + i) * HH + colq];
        float inv = 1.f / s;
        #pragma unroll
        for (int k = 0; k < 4; k++) {
            float4 a0 = *(const float4*)(&g_part[0][0] + rowo + 4 * k);
            float4 a1 = *(const float4*)(&g_part[1][0] + rowo + 4 * k);
            float4 xw = *(const float4*)(g_xW + rowo + 4 * k);
            v[k].x = (a0.x + a1.x) * inv + xw.x;
            v[k].y = (a0.y + a1.y) * inv + xw.y;
            v[k].z = (a0.z + a1.z) * inv + xw.z;
            v[k].w = (a0.w + a1.w) * inv + xw.w;
        }
    } else {
        #pragma unroll
        for (int k = 0; k < 4; k++) v[k] = make_float4(0.f, 0.f, 0.f, 0.f);
    }

    float s1 = 0.f, s2 = 0.f;
    #pragma unroll
    for (int k = 0; k < 4; k++) {
        s1 += v[k].x + v[k].y + v[k].z + v[k].w;
        s2 += v[k].x * v[k].x + v[k].y * v[k].y + v[k].z * v[k].z + v[k].w * v[k].w;
    }
    #pragma unroll
    for (int off = 1; off < 8; off <<= 1) {
        s1 += __shfl_xor_sync(0xffffffffu, s1, off);
        s2 += __shfl_xor_sync(0xffffffffu, s2, off);
    }
    float mu = s1 * (1.f / EE);
    float var = s2 * (1.f / EE) - mu * mu;
    float rstd = rsqrtf(var + LN_EPS);

    if (valid) {
        float* o = (dst < 0) ? dout : &g_x[dst][0];
        #pragma unroll
        for (int k = 0; k < 4; k++) {
            float4 gv = *(const float4*)&gamma[colq * 16 + 4 * k];
            float4 bv = *(const float4*)&beta[colq * 16 + 4 * k];
            float y0 = (v[k].x - mu) * rstd * gv.x + bv.x;
            float y1 = (v[k].y - mu) * rstd * gv.y + bv.y;
            float y2 = (v[k].z - mu) * rstd * gv.z + bv.z;
            float y3 = (v[k].w - mu) * rstd * gv.w + bv.w;
            y0 = y0 > 0.f ? y0 : (fast_exp(y0) - 1.f);
            y1 = y1 > 0.f ? y1 : (fast_exp(y1) - 1.f);
            y2 = y2 > 0.f ? y2 : (fast_exp(y2) - 1.f);
            y3 = y3 > 0.f ? y3 : (fast_exp(y3) - 1.f);
            *(float4*)(o + rowo + 4 * k) = make_float4(y0, y1, y2, y3);
        }
    }
}

// ---------------------------------------------------------------------------
extern "C" void kernel_launch(void* const* d_in, const int* in_sizes, int n_in,
                              void* d_out, int out_size) {
    const float* depot_xy = (const float*)d_in[0];
    const float* node5    = (const float*)d_in[1];
    const void*  adj_raw  = (const void*)d_in[2];
    const float* depW  = (const float*)d_in[3];
    const float* depb  = (const float*)d_in[4];
    const float* nodeW = (const float*)d_in[5];
    const float* nodeb = (const float*)d_in[6];
    const float* W     = (const float*)d_in[7];
    const float* attn  = (const float*)d_in[8];
    const float* ln_g  = (const float*)d_in[9];
    const float* ln_b  = (const float*)d_in[10];
    float* out = (float*)d_out;

    cudaFuncSetAttribute(xw_kernel,
                         cudaFuncAttributeMaxDynamicSharedMemorySize, XW_SMEM);
    cudaFuncSetAttribute(attn_kernel,
                         cudaFuncAttributeMaxDynamicSharedMemorySize, ATTN_SMEM);

    probe_mask_kernel<<<1, 256>>>((const unsigned int*)adj_raw);
    convert_bits_kernel<<<BB * NN, 512>>>(adj_raw);

    embed_kernel<<<BB * NN, EE>>>(depot_xy, node5, depW, depb, nodeW, nodeb);

    dim3 agrid((NN + IT - 1) / IT, BB, 2);
    dim3 cgrid((NN + IT - 1) / IT, BB);
    int cur = 0;
    for (int l = 0; l < LL; l++) {
        xw_kernel<<<XWGRID, 256, XW_SMEM>>>(cur,
                                            W + (size_t)l * EE * EE,
                                            attn + (size_t)l * HH * 2 * HD);
        gmax_kernel<<<BB, 256>>>();
        fact_kernel<<<(NFACT + 255) / 256, 256>>>();
        attn_kernel<<<agrid, 256, ATTN_SMEM>>>(0);
        int dst = (l == LL - 1) ? -1 : (1 - cur);
        combine_kernel<<<cgrid, 256>>>(ln_g + (size_t)l * EE,
                                       ln_b + (size_t)l * EE,
                                       dst, out);
        cur = 1 - cur;
    }
}